// round 1
// baseline (speedup 1.0000x reference)
#include <cuda_runtime.h>

#define BB 8
#define HH 64
#define WW 64
#define CC 256

// Scratch (allocation-free): qkv [32768 x 768], y [32768 x 256]
__device__ float g_qkv[25165824];
__device__ float g_y[8388608];

// C[M,N] = A[M,K] * B[N,K]^T + bias[N]
// BM=BN=128, BK=8, 256 threads, 8x8 micro-tile per thread.
__global__ __launch_bounds__(256)
void sgemm_nt(const float* __restrict__ A, const float* __restrict__ B,
              const float* __restrict__ bias, float* __restrict__ C,
              int Kd, int Nd)
{
    __shared__ float As[8][132];
    __shared__ float Bs[8][132];
    const int bm = blockIdx.y << 7;
    const int bn = blockIdx.x << 7;
    const int tid = threadIdx.x;
    const int tx = tid & 15;
    const int ty = tid >> 4;
    const int lr = tid >> 1;            // 0..127 tile row
    const int lc = (tid & 1) << 2;      // 0 or 4 k-offset

    const float* Ap = A + (size_t)(bm + lr) * Kd + lc;
    const float* Bp = B + (size_t)(bn + lr) * Kd + lc;

    float acc[8][8];
#pragma unroll
    for (int i = 0; i < 8; i++)
#pragma unroll
        for (int j = 0; j < 8; j++) acc[i][j] = 0.f;

    for (int k0 = 0; k0 < Kd; k0 += 8) {
        float4 av = *(const float4*)(Ap + k0);
        float4 bv = *(const float4*)(Bp + k0);
        As[lc + 0][lr] = av.x; As[lc + 1][lr] = av.y;
        As[lc + 2][lr] = av.z; As[lc + 3][lr] = av.w;
        Bs[lc + 0][lr] = bv.x; Bs[lc + 1][lr] = bv.y;
        Bs[lc + 2][lr] = bv.z; Bs[lc + 3][lr] = bv.w;
        __syncthreads();
#pragma unroll
        for (int kk = 0; kk < 8; kk++) {
            float4 a0 = *(const float4*)&As[kk][(ty << 2)];
            float4 a1 = *(const float4*)&As[kk][(ty << 2) + 64];
            float4 b0 = *(const float4*)&Bs[kk][(tx << 2)];
            float4 b1 = *(const float4*)&Bs[kk][(tx << 2) + 64];
            float a[8] = {a0.x, a0.y, a0.z, a0.w, a1.x, a1.y, a1.z, a1.w};
            float bb[8] = {b0.x, b0.y, b0.z, b0.w, b1.x, b1.y, b1.z, b1.w};
#pragma unroll
            for (int i = 0; i < 8; i++)
#pragma unroll
                for (int j = 0; j < 8; j++)
                    acc[i][j] = fmaf(a[i], bb[j], acc[i][j]);
        }
        __syncthreads();
    }

#pragma unroll
    for (int i = 0; i < 8; i++) {
        int row = bm + (ty << 2) + (i < 4 ? i : 60 + i);
#pragma unroll
        for (int jh = 0; jh < 2; jh++) {
            int col = bn + (tx << 2) + jh * 64;
            float4 o;
            o.x = acc[i][jh * 4 + 0] + __ldg(&bias[col + 0]);
            o.y = acc[i][jh * 4 + 1] + __ldg(&bias[col + 1]);
            o.z = acc[i][jh * 4 + 2] + __ldg(&bias[col + 2]);
            o.w = acc[i][jh * 4 + 3] + __ldg(&bias[col + 3]);
            *(float4*)&C[(size_t)row * Nd + col] = o;
        }
    }
}

// 2D neighborhood attention, one thread = one query position, D=32 in regs.
// grid: (W/16, H/8, B*4), block 128. head = head0 + (blockIdx.z & 3).
template<int K>
__global__ __launch_bounds__(128)
void natten_kernel(const float* __restrict__ rpb, int head0)
{
    constexpr int NHb = K / 2;
    constexpr int RP = 2 * K - 1;
    __shared__ float s_rpb[RP * RP];
    const int b  = blockIdx.z >> 2;
    const int hl = blockIdx.z & 3;
    const int h  = head0 + hl;
    const float* rp = rpb + (size_t)hl * RP * RP;
    for (int t = threadIdx.x; t < RP * RP; t += 128) s_rpb[t] = rp[t];
    __syncthreads();

    const int j = (blockIdx.x << 4) + (threadIdx.x & 15);
    const int i = (blockIdx.y << 3) + (threadIdx.x >> 4);

    const int si = min(max(i - NHb, 0), HH - K);
    const int sj = min(max(j - NHb, 0), WW - K);
    const int pi = (K - 1) + si - i;   // bias row start
    const int pj = (K - 1) + sj - j;   // bias col start

    const float scale = 0.17677669529663687f;  // 32^-0.5
    const float4* qp = (const float4*)&g_qkv[(size_t)((b * HH + i) * WW + j) * 768 + h * 32];
    float4 q[8];
#pragma unroll
    for (int t = 0; t < 8; t++) {
        q[t] = __ldg(&qp[t]);
        q[t].x *= scale; q[t].y *= scale; q[t].z *= scale; q[t].w *= scale;
    }

    float m = -1e30f, l = 0.f;
    float4 acc[8];
#pragma unroll
    for (int t = 0; t < 8; t++) acc[t] = make_float4(0.f, 0.f, 0.f, 0.f);

#pragma unroll 1
    for (int ki = 0; ki < K; ki++) {
        const float* kbase = &g_qkv[(size_t)((b * HH + si + ki) * WW + sj) * 768 + 256 + h * 32];
        const float* brow  = &s_rpb[(pi + ki) * RP + pj];
#pragma unroll 1
        for (int kj = 0; kj < K; kj++) {
            const float4* kp = (const float4*)(kbase + kj * 768);
            float dot = 0.f;
#pragma unroll
            for (int t = 0; t < 8; t++) {
                float4 kv = __ldg(&kp[t]);
                dot += q[t].x * kv.x + q[t].y * kv.y + q[t].z * kv.z + q[t].w * kv.w;
            }
            float s  = dot + brow[kj];
            float nm = fmaxf(m, s);
            float c  = __expf(m - nm);
            float p  = __expf(s - nm);
            l = l * c + p;
            m = nm;
#pragma unroll
            for (int t = 0; t < 8; t++) {
                float4 vv = __ldg(&kp[t + 64]);   // v = k + 256 floats
                acc[t].x = fmaf(acc[t].x, c, p * vv.x);
                acc[t].y = fmaf(acc[t].y, c, p * vv.y);
                acc[t].z = fmaf(acc[t].z, c, p * vv.z);
                acc[t].w = fmaf(acc[t].w, c, p * vv.w);
            }
        }
    }
    float inv = 1.f / l;
    float4* op = (float4*)&g_y[(size_t)((b * HH + i) * WW + j) * 256 + h * 32];
#pragma unroll
    for (int t = 0; t < 8; t++) {
        float4 o;
        o.x = acc[t].x * inv; o.y = acc[t].y * inv;
        o.z = acc[t].z * inv; o.w = acc[t].w * inv;
        op[t] = o;
    }
}

extern "C" void kernel_launch(void* const* d_in, const int* in_sizes, int n_in,
                              void* d_out, int out_size)
{
    const float* x      = (const float*)d_in[0];
    const float* w_qkv  = (const float*)d_in[1];
    const float* b_qkv  = (const float*)d_in[2];
    const float* rpb0   = (const float*)d_in[3];
    const float* rpb1   = (const float*)d_in[4];
    const float* w_proj = (const float*)d_in[5];
    const float* b_proj = (const float*)d_in[6];
    float* out = (float*)d_out;

    float* qkv = nullptr;
    float* y   = nullptr;
    cudaGetSymbolAddress((void**)&qkv, g_qkv);
    cudaGetSymbolAddress((void**)&y,   g_y);

    // 1) QKV GEMM: [32768,256] x [768,256]^T -> g_qkv
    sgemm_nt<<<dim3(6, 256), 256>>>(x, w_qkv, b_qkv, qkv, 256, 768);

    // 2) Neighborhood attention (split heads)
    natten_kernel<7> <<<dim3(4, 8, 32), 128>>>(rpb0, 0);
    natten_kernel<13><<<dim3(4, 8, 32), 128>>>(rpb1, 4);

    // 3) Projection GEMM: [32768,256] x [256,256]^T -> out
    sgemm_nt<<<dim3(2, 256), 256>>>(y, w_proj, b_proj, out, 256, 256);
}

// round 2
// speedup vs baseline: 2.7507x; 2.7507x over previous
#include <cuda_runtime.h>

#define BB 8
#define HH 64
#define WW 64
#define CC 256

// Scratch (allocation-free): qkv [32768 x 768], y [32768 x 256]
__device__ float g_qkv[25165824];
__device__ float g_y[8388608];

// C[M,N] = A[M,K] * B[N,K]^T + bias[N]
// BM=BN=128, BK=8, 256 threads, 8x8 micro-tile per thread.
__global__ __launch_bounds__(256)
void sgemm_nt(const float* __restrict__ A, const float* __restrict__ B,
              const float* __restrict__ bias, float* __restrict__ C,
              int Kd, int Nd)
{
    __shared__ float As[8][132];
    __shared__ float Bs[8][132];
    const int bm = blockIdx.y << 7;
    const int bn = blockIdx.x << 7;
    const int tid = threadIdx.x;
    const int tx = tid & 15;
    const int ty = tid >> 4;
    const int lr = tid >> 1;            // 0..127 tile row
    const int lc = (tid & 1) << 2;      // 0 or 4 k-offset

    const float* Ap = A + (size_t)(bm + lr) * Kd + lc;
    const float* Bp = B + (size_t)(bn + lr) * Kd + lc;

    float acc[8][8];
#pragma unroll
    for (int i = 0; i < 8; i++)
#pragma unroll
        for (int j = 0; j < 8; j++) acc[i][j] = 0.f;

    for (int k0 = 0; k0 < Kd; k0 += 8) {
        float4 av = *(const float4*)(Ap + k0);
        float4 bv = *(const float4*)(Bp + k0);
        As[lc + 0][lr] = av.x; As[lc + 1][lr] = av.y;
        As[lc + 2][lr] = av.z; As[lc + 3][lr] = av.w;
        Bs[lc + 0][lr] = bv.x; Bs[lc + 1][lr] = bv.y;
        Bs[lc + 2][lr] = bv.z; Bs[lc + 3][lr] = bv.w;
        __syncthreads();
#pragma unroll
        for (int kk = 0; kk < 8; kk++) {
            float4 a0 = *(const float4*)&As[kk][(ty << 2)];
            float4 a1 = *(const float4*)&As[kk][(ty << 2) + 64];
            float4 b0 = *(const float4*)&Bs[kk][(tx << 2)];
            float4 b1 = *(const float4*)&Bs[kk][(tx << 2) + 64];
            float a[8] = {a0.x, a0.y, a0.z, a0.w, a1.x, a1.y, a1.z, a1.w};
            float bb[8] = {b0.x, b0.y, b0.z, b0.w, b1.x, b1.y, b1.z, b1.w};
#pragma unroll
            for (int i = 0; i < 8; i++)
#pragma unroll
                for (int j = 0; j < 8; j++)
                    acc[i][j] = fmaf(a[i], bb[j], acc[i][j]);
        }
        __syncthreads();
    }

#pragma unroll
    for (int i = 0; i < 8; i++) {
        int row = bm + (ty << 2) + (i < 4 ? i : 60 + i);
#pragma unroll
        for (int jh = 0; jh < 2; jh++) {
            int col = bn + (tx << 2) + jh * 64;
            float4 o;
            o.x = acc[i][jh * 4 + 0] + __ldg(&bias[col + 0]);
            o.y = acc[i][jh * 4 + 1] + __ldg(&bias[col + 1]);
            o.z = acc[i][jh * 4 + 2] + __ldg(&bias[col + 2]);
            o.w = acc[i][jh * 4 + 3] + __ldg(&bias[col + 3]);
            *(float4*)&C[(size_t)row * Nd + col] = o;
        }
    }
}

// 2D neighborhood attention, quarter-warp (8 lanes) per query.
// Lane e of a quarter owns head dims [4e, 4e+4). K/V vector = 32 floats =
// 128B = one fully coalesced LDG.128 per quarter.
// Block 256 threads = 32 queries (half a row of consecutive j).
// grid: (4096/32, 1, B*4); head = head0 + (blockIdx.z & 3).
template<int K>
__global__ __launch_bounds__(256)
void natten_kernel(const float* __restrict__ rpb, int head0)
{
    constexpr int NHb = K / 2;
    constexpr int RP = 2 * K - 1;
    __shared__ float s_rpb[RP * RP];
    const int b  = blockIdx.z >> 2;
    const int hl = blockIdx.z & 3;
    const int h  = head0 + hl;
    const float* rp = rpb + (size_t)hl * RP * RP;
    for (int t = threadIdx.x; t < RP * RP; t += 256) s_rpb[t] = rp[t];
    __syncthreads();

    const int tid = threadIdx.x;
    const int e   = tid & 7;          // dim-slice lane within quarter
    const int qid = (blockIdx.x << 5) + (tid >> 3);
    const int i = qid >> 6;
    const int j = qid & 63;

    const int si = min(max(i - NHb, 0), HH - K);
    const int sj = min(max(j - NHb, 0), WW - K);
    const int pi = (K - 1) + si - i;   // bias row start
    const int pj = (K - 1) + sj - j;   // bias col start

    const float scale = 0.17677669529663687f;  // 32^-0.5
    float4 q = *(const float4*)&g_qkv[(size_t)((b * HH + i) * WW + j) * 768 + h * 32 + e * 4];
    q.x *= scale; q.y *= scale; q.z *= scale; q.w *= scale;

    float m = -1e30f, l = 0.f;
    float4 acc = make_float4(0.f, 0.f, 0.f, 0.f);

#pragma unroll 1
    for (int ki = 0; ki < K; ki++) {
        const float* krow = &g_qkv[(size_t)((b * HH + si + ki) * WW + sj) * 768 + 256 + h * 32 + e * 4];
        const float* brow = &s_rpb[(pi + ki) * RP + pj];
#pragma unroll
        for (int kj = 0; kj < K; kj++) {
            const float4 kv = *(const float4*)(krow + kj * 768);
            float r = q.x * kv.x + q.y * kv.y + q.z * kv.z + q.w * kv.w;
            r += __shfl_xor_sync(0xffffffffu, r, 1);
            r += __shfl_xor_sync(0xffffffffu, r, 2);
            r += __shfl_xor_sync(0xffffffffu, r, 4);
            const float s  = r + brow[kj];
            const float nm = fmaxf(m, s);
            const float c  = __expf(m - nm);
            const float p  = __expf(s - nm);
            l = l * c + p;
            m = nm;
            const float4 vv = *(const float4*)(krow + kj * 768 + 256);
            acc.x = fmaf(acc.x, c, p * vv.x);
            acc.y = fmaf(acc.y, c, p * vv.y);
            acc.z = fmaf(acc.z, c, p * vv.z);
            acc.w = fmaf(acc.w, c, p * vv.w);
        }
    }
    const float inv = 1.f / l;
    float4 o;
    o.x = acc.x * inv; o.y = acc.y * inv; o.z = acc.z * inv; o.w = acc.w * inv;
    *(float4*)&g_y[(size_t)((b * HH + i) * WW + j) * 256 + h * 32 + e * 4] = o;
}

extern "C" void kernel_launch(void* const* d_in, const int* in_sizes, int n_in,
                              void* d_out, int out_size)
{
    const float* x      = (const float*)d_in[0];
    const float* w_qkv  = (const float*)d_in[1];
    const float* b_qkv  = (const float*)d_in[2];
    const float* rpb0   = (const float*)d_in[3];
    const float* rpb1   = (const float*)d_in[4];
    const float* w_proj = (const float*)d_in[5];
    const float* b_proj = (const float*)d_in[6];
    float* out = (float*)d_out;

    float* qkv = nullptr;
    float* y   = nullptr;
    cudaGetSymbolAddress((void**)&qkv, g_qkv);
    cudaGetSymbolAddress((void**)&y,   g_y);

    // 1) QKV GEMM: [32768,256] x [768,256]^T -> g_qkv
    sgemm_nt<<<dim3(6, 256), 256>>>(x, w_qkv, b_qkv, qkv, 256, 768);

    // 2) Neighborhood attention (split heads), 32 queries / 256-thread block
    natten_kernel<7> <<<dim3(128, 1, 32), 256>>>(rpb0, 0);
    natten_kernel<13><<<dim3(128, 1, 32), 256>>>(rpb1, 4);

    // 3) Projection GEMM: [32768,256] x [256,256]^T -> out
    sgemm_nt<<<dim3(2, 256), 256>>>(y, w_proj, b_proj, out, 256, 256);
}

// round 4
// speedup vs baseline: 3.6171x; 1.3150x over previous
#include <cuda_runtime.h>
#include <cstdint>

#define BB 8
#define HH 64
#define WW 64

// Scratch (allocation-free): qkv [32768 x 768], y [32768 x 256]
__device__ float g_qkv[25165824];
__device__ float g_y[8388608];

__device__ __forceinline__ uint32_t f2tf32(float x) {
    uint32_t u;
    asm("cvt.rna.tf32.f32 %0, %1;" : "=r"(u) : "f"(x));
    return u;
}

// C[M,N] = A[M,K] * B[N,K]^T + bias[N], tf32 tensor cores, fp32 accum.
// BM=BN=128, BK=16, 256 threads = 8 warps (4m x 2n), warp tile 32x64.
__global__ __launch_bounds__(256)
void gemm_tf32(const float* __restrict__ A, const float* __restrict__ B,
               const float* __restrict__ bias, float* __restrict__ C,
               int Kd, int Nd)
{
    __shared__ uint32_t As[16][132];
    __shared__ uint32_t Bs[16][132];

    const int bm = blockIdx.y << 7;
    const int bn = blockIdx.x << 7;
    const int tid = threadIdx.x;

    // loaders: thread -> one row (0..127), k-half (0 or 8)
    const int lrow = tid >> 1;
    const int kh   = (tid & 1) << 3;
    const float* Ap = A + (size_t)(bm + lrow) * Kd + kh;
    const float* Bp = B + (size_t)(bn + lrow) * Kd + kh;

    // compute: warp tile
    const int wid = tid >> 5;
    const int lane = tid & 31;
    const int wm = (wid >> 1) << 5;     // 0,32,64,96
    const int wn = (wid & 1) << 6;      // 0,64
    const int lr = lane >> 2;           // 0..7
    const int lc = lane & 3;            // 0..3

    float acc[2][8][4];
#pragma unroll
    for (int mt = 0; mt < 2; mt++)
#pragma unroll
        for (int nt = 0; nt < 8; nt++)
#pragma unroll
            for (int r = 0; r < 4; r++) acc[mt][nt][r] = 0.f;

    float4 ra0 = *(const float4*)(Ap);
    float4 ra1 = *(const float4*)(Ap + 4);
    float4 rb0 = *(const float4*)(Bp);
    float4 rb1 = *(const float4*)(Bp + 4);

    for (int k0 = 0; k0 < Kd; k0 += 16) {
        As[kh + 0][lrow] = f2tf32(ra0.x);
        As[kh + 1][lrow] = f2tf32(ra0.y);
        As[kh + 2][lrow] = f2tf32(ra0.z);
        As[kh + 3][lrow] = f2tf32(ra0.w);
        As[kh + 4][lrow] = f2tf32(ra1.x);
        As[kh + 5][lrow] = f2tf32(ra1.y);
        As[kh + 6][lrow] = f2tf32(ra1.z);
        As[kh + 7][lrow] = f2tf32(ra1.w);
        Bs[kh + 0][lrow] = f2tf32(rb0.x);
        Bs[kh + 1][lrow] = f2tf32(rb0.y);
        Bs[kh + 2][lrow] = f2tf32(rb0.z);
        Bs[kh + 3][lrow] = f2tf32(rb0.w);
        Bs[kh + 4][lrow] = f2tf32(rb1.x);
        Bs[kh + 5][lrow] = f2tf32(rb1.y);
        Bs[kh + 6][lrow] = f2tf32(rb1.z);
        Bs[kh + 7][lrow] = f2tf32(rb1.w);
        __syncthreads();

        if (k0 + 16 < Kd) {
            ra0 = *(const float4*)(Ap + k0 + 16);
            ra1 = *(const float4*)(Ap + k0 + 20);
            rb0 = *(const float4*)(Bp + k0 + 16);
            rb1 = *(const float4*)(Bp + k0 + 20);
        }

#pragma unroll
        for (int kk = 0; kk < 16; kk += 8) {
            uint32_t af[2][4];
#pragma unroll
            for (int mt = 0; mt < 2; mt++) {
                const int m0 = wm + (mt << 4);
                af[mt][0] = As[kk + lc][m0 + lr];
                af[mt][1] = As[kk + lc][m0 + lr + 8];
                af[mt][2] = As[kk + lc + 4][m0 + lr];
                af[mt][3] = As[kk + lc + 4][m0 + lr + 8];
            }
#pragma unroll
            for (int nt = 0; nt < 8; nt++) {
                const int n0 = wn + (nt << 3);
                uint32_t b0 = Bs[kk + lc][n0 + lr];
                uint32_t b1 = Bs[kk + lc + 4][n0 + lr];
#pragma unroll
                for (int mt = 0; mt < 2; mt++) {
                    asm volatile(
                        "mma.sync.aligned.m16n8k8.row.col.f32.tf32.tf32.f32 "
                        "{%0,%1,%2,%3}, {%4,%5,%6,%7}, {%8,%9}, {%0,%1,%2,%3};\n"
                        : "+f"(acc[mt][nt][0]), "+f"(acc[mt][nt][1]),
                          "+f"(acc[mt][nt][2]), "+f"(acc[mt][nt][3])
                        : "r"(af[mt][0]), "r"(af[mt][1]), "r"(af[mt][2]), "r"(af[mt][3]),
                          "r"(b0), "r"(b1));
                }
            }
        }
        __syncthreads();
    }

    // epilogue: c0,c1 at (row, 2c), (row, 2c+1); c2,c3 at row+8
#pragma unroll
    for (int nt = 0; nt < 8; nt++) {
        const int col = bn + wn + (nt << 3) + (lc << 1);
        const float bx = __ldg(&bias[col]);
        const float by = __ldg(&bias[col + 1]);
#pragma unroll
        for (int mt = 0; mt < 2; mt++) {
            const int row = bm + wm + (mt << 4) + lr;
            float2 o0 = make_float2(acc[mt][nt][0] + bx, acc[mt][nt][1] + by);
            float2 o1 = make_float2(acc[mt][nt][2] + bx, acc[mt][nt][3] + by);
            *(float2*)&C[(size_t)row * Nd + col] = o0;
            *(float2*)&C[(size_t)(row + 8) * Nd + col] = o1;
        }
    }
}

// 2D neighborhood attention, quarter-warp (8 lanes) per query, row-wise
// online softmax (1 + K exps per window row instead of 2 per element).
// Block 256 threads = 32 queries. grid: (128, 1, B*4).
template<int K>
__global__ __launch_bounds__(256)
void natten_kernel(const float* __restrict__ rpb, int head0)
{
    constexpr int NHb = K / 2;
    constexpr int RP = 2 * K - 1;
    __shared__ float s_rpb[RP * RP];
    const int b  = blockIdx.z >> 2;
    const int hl = blockIdx.z & 3;
    const int h  = head0 + hl;
    const float* rp = rpb + (size_t)hl * RP * RP;
    for (int t = threadIdx.x; t < RP * RP; t += 256) s_rpb[t] = rp[t];
    __syncthreads();

    const int tid = threadIdx.x;
    const int e   = tid & 7;
    const int qid = (blockIdx.x << 5) + (tid >> 3);
    const int i = qid >> 6;
    const int j = qid & 63;

    const int si = min(max(i - NHb, 0), HH - K);
    const int sj = min(max(j - NHb, 0), WW - K);
    const int pi = (K - 1) + si - i;
    const int pj = (K - 1) + sj - j;

    const float scale = 0.17677669529663687f;  // 32^-0.5
    float4 q = *(const float4*)&g_qkv[(size_t)((b * HH + i) * WW + j) * 768 + h * 32 + e * 4];
    q.x *= scale; q.y *= scale; q.z *= scale; q.w *= scale;

    float m = -1e30f, l = 0.f;
    float4 acc = make_float4(0.f, 0.f, 0.f, 0.f);

#pragma unroll 1
    for (int ki = 0; ki < K; ki++) {
        const float* krow = &g_qkv[(size_t)((b * HH + si + ki) * WW + sj) * 768 + 256 + h * 32 + e * 4];
        const float* brow = &s_rpb[(pi + ki) * RP + pj];

        float s[K];
        float rowmax = -1e30f;
#pragma unroll
        for (int kj = 0; kj < K; kj++) {
            const float4 kv = *(const float4*)(krow + kj * 768);
            float r = q.x * kv.x + q.y * kv.y + q.z * kv.z + q.w * kv.w;
            r += __shfl_xor_sync(0xffffffffu, r, 1);
            r += __shfl_xor_sync(0xffffffffu, r, 2);
            r += __shfl_xor_sync(0xffffffffu, r, 4);
            s[kj] = r + brow[kj];
            rowmax = fmaxf(rowmax, s[kj]);
        }
        const float nm = fmaxf(m, rowmax);
        const float c  = __expf(m - nm);
        m = nm;
        l *= c;
        acc.x *= c; acc.y *= c; acc.z *= c; acc.w *= c;
#pragma unroll
        for (int kj = 0; kj < K; kj++) {
            const float p = __expf(s[kj] - nm);
            l += p;
            const float4 vv = *(const float4*)(krow + kj * 768 + 256);
            acc.x = fmaf(p, vv.x, acc.x);
            acc.y = fmaf(p, vv.y, acc.y);
            acc.z = fmaf(p, vv.z, acc.z);
            acc.w = fmaf(p, vv.w, acc.w);
        }
    }
    const float inv = 1.f / l;
    float4 o;
    o.x = acc.x * inv; o.y = acc.y * inv; o.z = acc.z * inv; o.w = acc.w * inv;
    *(float4*)&g_y[(size_t)((b * HH + i) * WW + j) * 256 + h * 32 + e * 4] = o;
}

extern "C" void kernel_launch(void* const* d_in, const int* in_sizes, int n_in,
                              void* d_out, int out_size)
{
    const float* x      = (const float*)d_in[0];
    const float* w_qkv  = (const float*)d_in[1];
    const float* b_qkv  = (const float*)d_in[2];
    const float* rpb0   = (const float*)d_in[3];
    const float* rpb1   = (const float*)d_in[4];
    const float* w_proj = (const float*)d_in[5];
    const float* b_proj = (const float*)d_in[6];
    float* out = (float*)d_out;

    float* qkv = nullptr;
    float* y   = nullptr;
    cudaGetSymbolAddress((void**)&qkv, g_qkv);
    cudaGetSymbolAddress((void**)&y,   g_y);

    // 1) QKV GEMM: [32768,256] x [768,256]^T -> g_qkv
    gemm_tf32<<<dim3(6, 256), 256>>>(x, w_qkv, b_qkv, qkv, 256, 768);

    // 2) Neighborhood attention (split heads)
    natten_kernel<7> <<<dim3(128, 1, 32), 256>>>(rpb0, 0);
    natten_kernel<13><<<dim3(128, 1, 32), 256>>>(rpb1, 4);

    // 3) Projection GEMM: [32768,256] x [256,256]^T -> out
    gemm_tf32<<<dim3(2, 256), 256>>>(y, w_proj, b_proj, out, 256, 256);
}

// round 5
// speedup vs baseline: 4.1490x; 1.1471x over previous
#include <cuda_runtime.h>
#include <cstdint>

#define BB 8
#define HH 64
#define WW 64

// Scratch: qkv [32768 x 768], y [32768 x 256], bias tables (mma-frag order)
__device__ float g_qkv[25165824];
__device__ float g_y[8388608];
__device__ float g_bias7[3670016];   // 4h*64t*4w*32l*28nt*4
__device__ float g_bias13[7864320];  // 4h*64t*4w*32l*60nt*4

__device__ __forceinline__ uint32_t f2tf32(float x) {
    uint32_t u;
    asm("cvt.rna.tf32.f32 %0, %1;" : "=r"(u) : "f"(x));
    return u;
}
__device__ __forceinline__ int iclamp(int v, int lo, int hi) {
    return min(max(v, lo), hi);
}

// ---------------------------------------------------------------------------
// GEMM (unchanged, known-good): C[M,N] = A[M,K]*B[N,K]^T + bias
// ---------------------------------------------------------------------------
__global__ __launch_bounds__(256)
void gemm_tf32(const float* __restrict__ A, const float* __restrict__ B,
               const float* __restrict__ bias, float* __restrict__ C,
               int Kd, int Nd)
{
    __shared__ uint32_t As[16][132];
    __shared__ uint32_t Bs[16][132];
    const int bm = blockIdx.y << 7;
    const int bn = blockIdx.x << 7;
    const int tid = threadIdx.x;
    const int lrow = tid >> 1;
    const int kh   = (tid & 1) << 3;
    const float* Ap = A + (size_t)(bm + lrow) * Kd + kh;
    const float* Bp = B + (size_t)(bn + lrow) * Kd + kh;
    const int wid = tid >> 5;
    const int lane = tid & 31;
    const int wm = (wid >> 1) << 5;
    const int wn = (wid & 1) << 6;
    const int lr = lane >> 2;
    const int lc = lane & 3;

    float acc[2][8][4];
#pragma unroll
    for (int mt = 0; mt < 2; mt++)
#pragma unroll
        for (int nt = 0; nt < 8; nt++)
#pragma unroll
            for (int r = 0; r < 4; r++) acc[mt][nt][r] = 0.f;

    float4 ra0 = *(const float4*)(Ap);
    float4 ra1 = *(const float4*)(Ap + 4);
    float4 rb0 = *(const float4*)(Bp);
    float4 rb1 = *(const float4*)(Bp + 4);

    for (int k0 = 0; k0 < Kd; k0 += 16) {
        As[kh + 0][lrow] = f2tf32(ra0.x); As[kh + 1][lrow] = f2tf32(ra0.y);
        As[kh + 2][lrow] = f2tf32(ra0.z); As[kh + 3][lrow] = f2tf32(ra0.w);
        As[kh + 4][lrow] = f2tf32(ra1.x); As[kh + 5][lrow] = f2tf32(ra1.y);
        As[kh + 6][lrow] = f2tf32(ra1.z); As[kh + 7][lrow] = f2tf32(ra1.w);
        Bs[kh + 0][lrow] = f2tf32(rb0.x); Bs[kh + 1][lrow] = f2tf32(rb0.y);
        Bs[kh + 2][lrow] = f2tf32(rb0.z); Bs[kh + 3][lrow] = f2tf32(rb0.w);
        Bs[kh + 4][lrow] = f2tf32(rb1.x); Bs[kh + 5][lrow] = f2tf32(rb1.y);
        Bs[kh + 6][lrow] = f2tf32(rb1.z); Bs[kh + 7][lrow] = f2tf32(rb1.w);
        __syncthreads();
        if (k0 + 16 < Kd) {
            ra0 = *(const float4*)(Ap + k0 + 16);
            ra1 = *(const float4*)(Ap + k0 + 20);
            rb0 = *(const float4*)(Bp + k0 + 16);
            rb1 = *(const float4*)(Bp + k0 + 20);
        }
#pragma unroll
        for (int kk = 0; kk < 16; kk += 8) {
            uint32_t af[2][4];
#pragma unroll
            for (int mt = 0; mt < 2; mt++) {
                const int m0 = wm + (mt << 4);
                af[mt][0] = As[kk + lc][m0 + lr];
                af[mt][1] = As[kk + lc][m0 + lr + 8];
                af[mt][2] = As[kk + lc + 4][m0 + lr];
                af[mt][3] = As[kk + lc + 4][m0 + lr + 8];
            }
#pragma unroll
            for (int nt = 0; nt < 8; nt++) {
                const int n0 = wn + (nt << 3);
                uint32_t b0 = Bs[kk + lc][n0 + lr];
                uint32_t b1 = Bs[kk + lc + 4][n0 + lr];
#pragma unroll
                for (int mt = 0; mt < 2; mt++) {
                    asm volatile(
                        "mma.sync.aligned.m16n8k8.row.col.f32.tf32.tf32.f32 "
                        "{%0,%1,%2,%3}, {%4,%5,%6,%7}, {%8,%9}, {%0,%1,%2,%3};\n"
                        : "+f"(acc[mt][nt][0]), "+f"(acc[mt][nt][1]),
                          "+f"(acc[mt][nt][2]), "+f"(acc[mt][nt][3])
                        : "r"(af[mt][0]), "r"(af[mt][1]), "r"(af[mt][2]), "r"(af[mt][3]),
                          "r"(b0), "r"(b1));
                }
            }
        }
        __syncthreads();
    }
#pragma unroll
    for (int nt = 0; nt < 8; nt++) {
        const int col = bn + wn + (nt << 3) + (lc << 1);
        const float bx = __ldg(&bias[col]);
        const float by = __ldg(&bias[col + 1]);
#pragma unroll
        for (int mt = 0; mt < 2; mt++) {
            const int row = bm + wm + (mt << 4) + lr;
            *(float2*)&C[(size_t)row * Nd + col] =
                make_float2(acc[mt][nt][0] + bx, acc[mt][nt][1] + by);
            *(float2*)&C[(size_t)(row + 8) * Nd + col] =
                make_float2(acc[mt][nt][2] + bx, acc[mt][nt][3] + by);
        }
    }
}

// ---------------------------------------------------------------------------
// Bias+mask table precompute: one float4 per (h,tile,warp,lane,ntile),
// in exact mma accumulator register order (c0,c1,c2,c3).
// ---------------------------------------------------------------------------
template<int K, int UXP, int UXR, int NTILES>
__global__ __launch_bounds__(256)
void bias_precompute(const float* __restrict__ rpb, float* __restrict__ table)
{
    constexpr int NH = K / 2;
    constexpr int RP = 2 * K - 1;
    constexpr int UY = K + 7;
    const int gid = blockIdx.x * 256 + threadIdx.x;
    const int total = 4 * 64 * 128 * NTILES;
    if (gid >= total) return;
    const int t    = gid % NTILES;
    int r1 = gid / NTILES;
    const int lane = r1 & 31; r1 >>= 5;
    const int w    = r1 & 3;  r1 >>= 2;
    const int tile = r1 & 63; r1 >>= 6;
    const int h    = r1;
    const int ty = tile >> 3, tx = tile & 7;
    const int lr = lane >> 2, lc = lane & 3;
    const int uy0 = iclamp(ty * 8 - NH, 0, HH - UY);
    const int ux0 = iclamp(tx * 8 - NH, 0, WW - UY);

    float v[4];
#pragma unroll
    for (int r = 0; r < 4; r++) {
        const int m = w * 16 + lr + ((r >> 1) << 3);
        const int n = t * 8 + (lc << 1) + (r & 1);
        const int i = ty * 8 + (m >> 3);
        const int j = tx * 8 + (m & 7);
        const int si = iclamp(i - NH, 0, HH - K);
        const int sj = iclamp(j - NH, 0, WW - K);
        const int uy = n / UXP, ux = n % UXP;
        const int y = uy0 + uy, x = ux0 + ux;
        bool ok = (ux < UXR) && (y >= si) && (y < si + K) && (x >= sj) && (x < sj + K);
        v[r] = ok ? rpb[((size_t)h * RP + (y - i + K - 1)) * RP + (x - j + K - 1)]
                  : -1e30f;
    }
    *(float4*)&table[(size_t)gid * 4] = make_float4(v[0], v[1], v[2], v[3]);
}

// ---------------------------------------------------------------------------
// Tensor-core NATTEN: block = (b, head, 8x8 query tile), 128 threads (4 warps,
// warp owns 16 queries). Online softmax over NC key chunks of NT n-tiles.
// ---------------------------------------------------------------------------
template<int K, int UXP, int UXR, int NT, int NC, int SK, int SV>
__global__ __launch_bounds__(128)
void natten_mma(const float* __restrict__ bias_table, int head0)
{
    constexpr int NH = K / 2;
    constexpr int UY = K + 7;
    constexpr int CP = NT * 8;       // keys per chunk
    constexpr int NTILES = NT * NC;
    constexpr int OQ = 0;            // Qs[32][72]
    constexpr int OK = 2304;         // Ks[32][SK]
    constexpr int OV = OK + 32 * SK; // Vs[32][SV]
    constexpr int OP = OV + 32 * SV; // Ps[4][CP][24]

    extern __shared__ float sm[];
    uint32_t* smu = (uint32_t*)sm;

    const int b    = blockIdx.z;
    const int hl   = blockIdx.y;
    const int h    = head0 + hl;
    const int tile = blockIdx.x;
    const int ty = tile >> 3, tx = tile & 7;
    const int uy0 = iclamp(ty * 8 - NH, 0, HH - UY);
    const int ux0 = iclamp(tx * 8 - NH, 0, WW - UY);

    const int tid  = threadIdx.x;
    const int w    = tid >> 5;
    const int lane = tid & 31;
    const int lr = lane >> 2, lc = lane & 3;
    const int m0 = w << 4;

    // ---- stage Q (scaled, tf32) into Qs[k][m], stride 72 ----
    {
        const int qm = tid >> 1;
        const int kh = (tid & 1) << 4;
        const int qi = ty * 8 + (qm >> 3);
        const int qj = tx * 8 + (qm & 7);
        const float4* qp = (const float4*)&g_qkv[(size_t)((b * HH + qi) * WW + qj) * 768 + h * 32 + kh];
        const float scale = 0.17677669529663687f;
#pragma unroll
        for (int v4 = 0; v4 < 4; v4++) {
            float4 qv = __ldg(&qp[v4]);
            smu[OQ + (kh + v4 * 4 + 0) * 72 + qm] = f2tf32(qv.x * scale);
            smu[OQ + (kh + v4 * 4 + 1) * 72 + qm] = f2tf32(qv.y * scale);
            smu[OQ + (kh + v4 * 4 + 2) * 72 + qm] = f2tf32(qv.z * scale);
            smu[OQ + (kh + v4 * 4 + 3) * 72 + qm] = f2tf32(qv.w * scale);
        }
    }
    __syncthreads();

    uint32_t qf[4][4];
#pragma unroll
    for (int s = 0; s < 4; s++) {
        qf[s][0] = smu[OQ + (8 * s + lc) * 72 + m0 + lr];
        qf[s][1] = smu[OQ + (8 * s + lc) * 72 + m0 + lr + 8];
        qf[s][2] = smu[OQ + (8 * s + lc + 4) * 72 + m0 + lr];
        qf[s][3] = smu[OQ + (8 * s + lc + 4) * 72 + m0 + lr + 8];
    }

    float mr0 = -1e28f, mr1 = -1e28f, l0 = 0.f, l1 = 0.f;
    float o[4][4];
#pragma unroll
    for (int nt = 0; nt < 4; nt++)
#pragma unroll
        for (int r = 0; r < 4; r++) o[nt][r] = 0.f;

    const float4* bt = (const float4*)bias_table +
        ((size_t)(((hl * 64 + tile) * 4 + w) * 32 + lane)) * NTILES;

    uint32_t* Pw = smu + OP + w * CP * 24;

    for (int c = 0; c < NC; c++) {
        __syncthreads();
        // ---- load K/V chunk into Ks[dim][pos] / Vs[dim][pos] (tf32) ----
        {
            const int e = tid & 7;
#pragma unroll 1
            for (int p = tid >> 3; p < CP; p += 16) {
                const int n = c * CP + p;
                const int uy = n / UXP, ux = n % UXP;
                const int y = uy0 + uy;
                const int x = min(ux0 + ux, WW - 1);
                const float* kp = &g_qkv[(size_t)((b * HH + y) * WW + x) * 768 + 256 + h * 32 + e * 4];
                float4 kv = __ldg((const float4*)kp);
                float4 vv = __ldg((const float4*)(kp + 256));
                smu[OK + (4 * e + 0) * SK + p] = f2tf32(kv.x);
                smu[OK + (4 * e + 1) * SK + p] = f2tf32(kv.y);
                smu[OK + (4 * e + 2) * SK + p] = f2tf32(kv.z);
                smu[OK + (4 * e + 3) * SK + p] = f2tf32(kv.w);
                smu[OV + (4 * e + 0) * SV + p] = f2tf32(vv.x);
                smu[OV + (4 * e + 1) * SV + p] = f2tf32(vv.y);
                smu[OV + (4 * e + 2) * SV + p] = f2tf32(vv.z);
                smu[OV + (4 * e + 3) * SV + p] = f2tf32(vv.w);
            }
        }
        __syncthreads();

        // ---- S = Q K^T ----
        float s[NT][4];
#pragma unroll
        for (int t = 0; t < NT; t++)
#pragma unroll
            for (int r = 0; r < 4; r++) s[t][r] = 0.f;
#pragma unroll
        for (int t = 0; t < NT; t++) {
#pragma unroll
            for (int kk = 0; kk < 4; kk++) {
                uint32_t b0 = smu[OK + (8 * kk + lc) * SK + 8 * t + lr];
                uint32_t b1 = smu[OK + (8 * kk + lc + 4) * SK + 8 * t + lr];
                asm volatile(
                    "mma.sync.aligned.m16n8k8.row.col.f32.tf32.tf32.f32 "
                    "{%0,%1,%2,%3}, {%4,%5,%6,%7}, {%8,%9}, {%0,%1,%2,%3};\n"
                    : "+f"(s[t][0]), "+f"(s[t][1]), "+f"(s[t][2]), "+f"(s[t][3])
                    : "r"(qf[kk][0]), "r"(qf[kk][1]), "r"(qf[kk][2]), "r"(qf[kk][3]),
                      "r"(b0), "r"(b1));
            }
        }
        // ---- + bias/mask (precomputed, frag-ordered) ----
#pragma unroll
        for (int t = 0; t < NT; t++) {
            float4 bv = __ldg(&bt[c * NT + t]);
            s[t][0] += bv.x; s[t][1] += bv.y; s[t][2] += bv.z; s[t][3] += bv.w;
        }
        // ---- online softmax ----
        float rm0 = -1e30f, rm1 = -1e30f;
#pragma unroll
        for (int t = 0; t < NT; t++) {
            rm0 = fmaxf(rm0, fmaxf(s[t][0], s[t][1]));
            rm1 = fmaxf(rm1, fmaxf(s[t][2], s[t][3]));
        }
        rm0 = fmaxf(rm0, __shfl_xor_sync(0xffffffffu, rm0, 1));
        rm0 = fmaxf(rm0, __shfl_xor_sync(0xffffffffu, rm0, 2));
        rm1 = fmaxf(rm1, __shfl_xor_sync(0xffffffffu, rm1, 1));
        rm1 = fmaxf(rm1, __shfl_xor_sync(0xffffffffu, rm1, 2));
        const float nm0 = fmaxf(mr0, rm0);
        const float nm1 = fmaxf(mr1, rm1);
        const float c0 = __expf(mr0 - nm0);
        const float c1 = __expf(mr1 - nm1);
        mr0 = nm0; mr1 = nm1;
        l0 *= c0; l1 *= c1;
#pragma unroll
        for (int nt = 0; nt < 4; nt++) {
            o[nt][0] *= c0; o[nt][1] *= c0;
            o[nt][2] *= c1; o[nt][3] *= c1;
        }
#pragma unroll
        for (int t = 0; t < NT; t++) {
            float p0 = __expf(s[t][0] - nm0);
            float p1 = __expf(s[t][1] - nm0);
            float p2 = __expf(s[t][2] - nm1);
            float p3 = __expf(s[t][3] - nm1);
            l0 += p0 + p1; l1 += p2 + p3;
            Pw[(8 * t + 2 * lc) * 24 + lr]         = f2tf32(p0);
            Pw[(8 * t + 2 * lc + 1) * 24 + lr]     = f2tf32(p1);
            Pw[(8 * t + 2 * lc) * 24 + lr + 8]     = f2tf32(p2);
            Pw[(8 * t + 2 * lc + 1) * 24 + lr + 8] = f2tf32(p3);
        }
        __syncwarp();
        // ---- O += P V ----
#pragma unroll
        for (int kk = 0; kk < NT; kk++) {
            uint32_t pa0 = Pw[(8 * kk + lc) * 24 + lr];
            uint32_t pa1 = Pw[(8 * kk + lc) * 24 + lr + 8];
            uint32_t pa2 = Pw[(8 * kk + lc + 4) * 24 + lr];
            uint32_t pa3 = Pw[(8 * kk + lc + 4) * 24 + lr + 8];
#pragma unroll
            for (int nt = 0; nt < 4; nt++) {
                uint32_t b0 = smu[OV + (8 * nt + lr) * SV + 8 * kk + lc];
                uint32_t b1 = smu[OV + (8 * nt + lr) * SV + 8 * kk + lc + 4];
                asm volatile(
                    "mma.sync.aligned.m16n8k8.row.col.f32.tf32.tf32.f32 "
                    "{%0,%1,%2,%3}, {%4,%5,%6,%7}, {%8,%9}, {%0,%1,%2,%3};\n"
                    : "+f"(o[nt][0]), "+f"(o[nt][1]), "+f"(o[nt][2]), "+f"(o[nt][3])
                    : "r"(pa0), "r"(pa1), "r"(pa2), "r"(pa3), "r"(b0), "r"(b1));
            }
        }
        __syncwarp();
    }

    // ---- finalize ----
    l0 += __shfl_xor_sync(0xffffffffu, l0, 1);
    l0 += __shfl_xor_sync(0xffffffffu, l0, 2);
    l1 += __shfl_xor_sync(0xffffffffu, l1, 1);
    l1 += __shfl_xor_sync(0xffffffffu, l1, 2);
    const float inv0 = 1.f / l0;
    const float inv1 = 1.f / l1;
    const int i0 = ty * 8 + 2 * w;
    const int j  = tx * 8 + lr;
    float* y0 = &g_y[(size_t)((b * HH + i0) * WW + j) * 256 + h * 32];
    float* y1 = &g_y[(size_t)((b * HH + i0 + 1) * WW + j) * 256 + h * 32];
#pragma unroll
    for (int nt = 0; nt < 4; nt++) {
        const int d = 8 * nt + 2 * lc;
        *(float2*)&y0[d] = make_float2(o[nt][0] * inv0, o[nt][1] * inv0);
        *(float2*)&y1[d] = make_float2(o[nt][2] * inv1, o[nt][3] * inv1);
    }
}

// ---------------------------------------------------------------------------
extern "C" void kernel_launch(void* const* d_in, const int* in_sizes, int n_in,
                              void* d_out, int out_size)
{
    const float* x      = (const float*)d_in[0];
    const float* w_qkv  = (const float*)d_in[1];
    const float* b_qkv  = (const float*)d_in[2];
    const float* rpb0   = (const float*)d_in[3];
    const float* rpb1   = (const float*)d_in[4];
    const float* w_proj = (const float*)d_in[5];
    const float* b_proj = (const float*)d_in[6];
    float* out = (float*)d_out;

    float *qkv = nullptr, *y = nullptr, *bt7 = nullptr, *bt13 = nullptr;
    cudaGetSymbolAddress((void**)&qkv,  g_qkv);
    cudaGetSymbolAddress((void**)&y,    g_y);
    cudaGetSymbolAddress((void**)&bt7,  g_bias7);
    cudaGetSymbolAddress((void**)&bt13, g_bias13);

    // natten<13> needs 62KB dynamic smem (idempotent attribute set)
    cudaFuncSetAttribute(natten_mma<13, 24, 20, 10, 6, 88, 84>,
                         cudaFuncAttributeMaxDynamicSharedMemorySize, 64 * 1024);

    // bias/mask tables (batch-independent, frag-ordered)
    bias_precompute<7, 16, 14, 28><<<3584, 256>>>(rpb0, bt7);
    bias_precompute<13, 24, 20, 60><<<7680, 256>>>(rpb1, bt13);

    // 1) QKV GEMM
    gemm_tf32<<<dim3(6, 256), 256>>>(x, w_qkv, b_qkv, qkv, 256, 768);

    // 2) tensor-core neighborhood attention (split heads)
    natten_mma<7, 16, 14, 7, 4, 56, 60>
        <<<dim3(64, 4, 8), 128, 45568>>>(bt7, 0);
    natten_mma<13, 24, 20, 10, 6, 88, 84>
        <<<dim3(64, 4, 8), 128, 61952>>>(bt13, 4);

    // 3) Projection GEMM
    gemm_tf32<<<dim3(2, 256), 256>>>(y, w_proj, b_proj, out, 256, 256);
}

// round 6
// speedup vs baseline: 4.6380x; 1.1179x over previous
#include <cuda_runtime.h>
#include <cstdint>

#define BB 8
#define HH 64
#define WW 64

// Scratch: qkv [32768 x 768], y [32768 x 256], bias tables (mma-frag order)
__device__ float g_qkv[25165824];
__device__ float g_y[8388608];
__device__ float g_bias7[3670016];   // 4h*64t*4w*32l*28nt*4
__device__ float g_bias13[7864320];  // 4h*64t*4w*32l*60nt*4

__device__ __forceinline__ uint32_t f2tf32(float x) {
    uint32_t u;
    asm("cvt.rna.tf32.f32 %0, %1;" : "=r"(u) : "f"(x));
    return u;
}
__device__ __forceinline__ int iclamp(int v, int lo, int hi) {
    return min(max(v, lo), hi);
}

// ---------------------------------------------------------------------------
// GEMM: C[M,N] = A[M,K]*B[N,K]^T + bias, tf32 mma, double-buffered smem.
// BM=BN=128, BK=16, 256 threads = 8 warps (4m x 2n), warp tile 32x64.
// ---------------------------------------------------------------------------
__global__ __launch_bounds__(256)
void gemm_tf32(const float* __restrict__ A, const float* __restrict__ B,
               const float* __restrict__ bias, float* __restrict__ C,
               int Kd, int Nd)
{
    __shared__ uint32_t As[2][16][132];
    __shared__ uint32_t Bs[2][16][132];
    const int bm = blockIdx.y << 7;
    const int bn = blockIdx.x << 7;
    const int tid = threadIdx.x;

    // loader: float4-granular. row = tid>>2 (+64), kc = (tid&3)*4
    const int lrow = tid >> 2;
    const int lkc  = (tid & 3) << 2;
    const float* Ap0 = A + (size_t)(bm + lrow) * Kd + lkc;
    const float* Ap1 = A + (size_t)(bm + lrow + 64) * Kd + lkc;
    const float* Bp0 = B + (size_t)(bn + lrow) * Kd + lkc;
    const float* Bp1 = B + (size_t)(bn + lrow + 64) * Kd + lkc;

    const int wid = tid >> 5;
    const int lane = tid & 31;
    const int wm = (wid >> 1) << 5;
    const int wn = (wid & 1) << 6;
    const int lr = lane >> 2;
    const int lc = lane & 3;

    float acc[2][8][4];
#pragma unroll
    for (int mt = 0; mt < 2; mt++)
#pragma unroll
        for (int nt = 0; nt < 8; nt++)
#pragma unroll
            for (int r = 0; r < 4; r++) acc[mt][nt][r] = 0.f;

    float4 ra0 = *(const float4*)(Ap0);
    float4 ra1 = *(const float4*)(Ap1);
    float4 rb0 = *(const float4*)(Bp0);
    float4 rb1 = *(const float4*)(Bp1);

#define GSTORE(st)                                                        \
    do {                                                                  \
        As[st][lkc + 0][lrow] = f2tf32(ra0.x);                            \
        As[st][lkc + 1][lrow] = f2tf32(ra0.y);                            \
        As[st][lkc + 2][lrow] = f2tf32(ra0.z);                            \
        As[st][lkc + 3][lrow] = f2tf32(ra0.w);                            \
        As[st][lkc + 0][lrow + 64] = f2tf32(ra1.x);                       \
        As[st][lkc + 1][lrow + 64] = f2tf32(ra1.y);                       \
        As[st][lkc + 2][lrow + 64] = f2tf32(ra1.z);                       \
        As[st][lkc + 3][lrow + 64] = f2tf32(ra1.w);                       \
        Bs[st][lkc + 0][lrow] = f2tf32(rb0.x);                            \
        Bs[st][lkc + 1][lrow] = f2tf32(rb0.y);                            \
        Bs[st][lkc + 2][lrow] = f2tf32(rb0.z);                            \
        Bs[st][lkc + 3][lrow] = f2tf32(rb0.w);                            \
        Bs[st][lkc + 0][lrow + 64] = f2tf32(rb1.x);                       \
        Bs[st][lkc + 1][lrow + 64] = f2tf32(rb1.y);                       \
        Bs[st][lkc + 2][lrow + 64] = f2tf32(rb1.z);                       \
        Bs[st][lkc + 3][lrow + 64] = f2tf32(rb1.w);                       \
    } while (0)

    GSTORE(0);
    __syncthreads();

    const int NIT = Kd >> 4;
    for (int it = 0; it < NIT; it++) {
        const int cur = it & 1;
        if (it + 1 < NIT) {
            const int ko = (it + 1) << 4;
            ra0 = *(const float4*)(Ap0 + ko);
            ra1 = *(const float4*)(Ap1 + ko);
            rb0 = *(const float4*)(Bp0 + ko);
            rb1 = *(const float4*)(Bp1 + ko);
        }
#pragma unroll
        for (int kk = 0; kk < 16; kk += 8) {
            uint32_t af[2][4];
#pragma unroll
            for (int mt = 0; mt < 2; mt++) {
                const int m0 = wm + (mt << 4);
                af[mt][0] = As[cur][kk + lc][m0 + lr];
                af[mt][1] = As[cur][kk + lc][m0 + lr + 8];
                af[mt][2] = As[cur][kk + lc + 4][m0 + lr];
                af[mt][3] = As[cur][kk + lc + 4][m0 + lr + 8];
            }
#pragma unroll
            for (int nt = 0; nt < 8; nt++) {
                const int n0 = wn + (nt << 3);
                uint32_t b0 = Bs[cur][kk + lc][n0 + lr];
                uint32_t b1 = Bs[cur][kk + lc + 4][n0 + lr];
#pragma unroll
                for (int mt = 0; mt < 2; mt++) {
                    asm volatile(
                        "mma.sync.aligned.m16n8k8.row.col.f32.tf32.tf32.f32 "
                        "{%0,%1,%2,%3}, {%4,%5,%6,%7}, {%8,%9}, {%0,%1,%2,%3};\n"
                        : "+f"(acc[mt][nt][0]), "+f"(acc[mt][nt][1]),
                          "+f"(acc[mt][nt][2]), "+f"(acc[mt][nt][3])
                        : "r"(af[mt][0]), "r"(af[mt][1]), "r"(af[mt][2]), "r"(af[mt][3]),
                          "r"(b0), "r"(b1));
                }
            }
        }
        if (it + 1 < NIT) GSTORE(cur ^ 1);
        __syncthreads();
    }
#undef GSTORE

#pragma unroll
    for (int nt = 0; nt < 8; nt++) {
        const int col = bn + wn + (nt << 3) + (lc << 1);
        const float bx = __ldg(&bias[col]);
        const float by = __ldg(&bias[col + 1]);
#pragma unroll
        for (int mt = 0; mt < 2; mt++) {
            const int row = bm + wm + (mt << 4) + lr;
            *(float2*)&C[(size_t)row * Nd + col] =
                make_float2(acc[mt][nt][0] + bx, acc[mt][nt][1] + by);
            *(float2*)&C[(size_t)(row + 8) * Nd + col] =
                make_float2(acc[mt][nt][2] + bx, acc[mt][nt][3] + by);
        }
    }
}

// ---------------------------------------------------------------------------
// Bias+mask table precompute (unchanged): frag-ordered float4 per
// (h,tile,warp,lane,ntile).
// ---------------------------------------------------------------------------
template<int K, int UXP, int UXR, int NTILES>
__global__ __launch_bounds__(256)
void bias_precompute(const float* __restrict__ rpb, float* __restrict__ table)
{
    constexpr int NH = K / 2;
    constexpr int RP = 2 * K - 1;
    constexpr int UY = K + 7;
    const int gid = blockIdx.x * 256 + threadIdx.x;
    const int total = 4 * 64 * 128 * NTILES;
    if (gid >= total) return;
    const int t    = gid % NTILES;
    int r1 = gid / NTILES;
    const int lane = r1 & 31; r1 >>= 5;
    const int w    = r1 & 3;  r1 >>= 2;
    const int tile = r1 & 63; r1 >>= 6;
    const int h    = r1;
    const int ty = tile >> 3, tx = tile & 7;
    const int lr = lane >> 2, lc = lane & 3;
    const int uy0 = iclamp(ty * 8 - NH, 0, HH - UY);
    const int ux0 = iclamp(tx * 8 - NH, 0, WW - UY);

    float v[4];
#pragma unroll
    for (int r = 0; r < 4; r++) {
        const int m = w * 16 + lr + ((r >> 1) << 3);
        const int n = t * 8 + (lc << 1) + (r & 1);
        const int i = ty * 8 + (m >> 3);
        const int j = tx * 8 + (m & 7);
        const int si = iclamp(i - NH, 0, HH - K);
        const int sj = iclamp(j - NH, 0, WW - K);
        const int uy = n / UXP, ux = n % UXP;
        const int y = uy0 + uy, x = ux0 + ux;
        bool ok = (ux < UXR) && (y >= si) && (y < si + K) && (x >= sj) && (x < sj + K);
        v[r] = ok ? rpb[((size_t)h * RP + (y - i + K - 1)) * RP + (x - j + K - 1)]
                  : -1e30f;
    }
    *(float4*)&table[(size_t)gid * 4] = make_float4(v[0], v[1], v[2], v[3]);
}

// ---------------------------------------------------------------------------
// Tensor-core NATTEN. K/V staged [pos][dim] with packed STS.128:
// Ks stride 36 (S-frag loads conflict-free), Vs stride 40 (PV-frag loads
// conflict-free). Block = (b, head, 8x8 query tile), 128 threads.
// ---------------------------------------------------------------------------
template<int K, int UXP, int UXR, int NT, int NC>
__global__ __launch_bounds__(128)
void natten_mma(const float* __restrict__ bias_table, int head0)
{
    constexpr int NH = K / 2;
    constexpr int UY = K + 7;
    constexpr int CP = NT * 8;        // keys per chunk
    constexpr int NTILES = NT * NC;
    constexpr int OQ = 0;             // Qs[32][72]
    constexpr int OK = 2304;          // Ks[CP][36]
    constexpr int OV = OK + CP * 36;  // Vs[CP][40]
    constexpr int OP = OV + CP * 40;  // Ps[4][CP][24]

    extern __shared__ float sm[];
    uint32_t* smu = (uint32_t*)sm;

    const int b    = blockIdx.z;
    const int hl   = blockIdx.y;
    const int h    = head0 + hl;
    const int tile = blockIdx.x;
    const int ty = tile >> 3, tx = tile & 7;
    const int uy0 = iclamp(ty * 8 - NH, 0, HH - UY);
    const int ux0 = iclamp(tx * 8 - NH, 0, WW - UY);

    const int tid  = threadIdx.x;
    const int w    = tid >> 5;
    const int lane = tid & 31;
    const int lr = lane >> 2, lc = lane & 3;
    const int m0 = w << 4;

    // ---- stage Q (scaled, tf32) into Qs[k][m], stride 72 ----
    {
        const int qm = tid >> 1;
        const int kh = (tid & 1) << 4;
        const int qi = ty * 8 + (qm >> 3);
        const int qj = tx * 8 + (qm & 7);
        const float4* qp = (const float4*)&g_qkv[(size_t)((b * HH + qi) * WW + qj) * 768 + h * 32 + kh];
        const float scale = 0.17677669529663687f;
#pragma unroll
        for (int v4 = 0; v4 < 4; v4++) {
            float4 qv = __ldg(&qp[v4]);
            smu[OQ + (kh + v4 * 4 + 0) * 72 + qm] = f2tf32(qv.x * scale);
            smu[OQ + (kh + v4 * 4 + 1) * 72 + qm] = f2tf32(qv.y * scale);
            smu[OQ + (kh + v4 * 4 + 2) * 72 + qm] = f2tf32(qv.z * scale);
            smu[OQ + (kh + v4 * 4 + 3) * 72 + qm] = f2tf32(qv.w * scale);
        }
    }
    __syncthreads();

    uint32_t qf[4][4];
#pragma unroll
    for (int s = 0; s < 4; s++) {
        qf[s][0] = smu[OQ + (8 * s + lc) * 72 + m0 + lr];
        qf[s][1] = smu[OQ + (8 * s + lc) * 72 + m0 + lr + 8];
        qf[s][2] = smu[OQ + (8 * s + lc + 4) * 72 + m0 + lr];
        qf[s][3] = smu[OQ + (8 * s + lc + 4) * 72 + m0 + lr + 8];
    }

    float mr0 = -1e28f, mr1 = -1e28f, l0 = 0.f, l1 = 0.f;
    float o[4][4];
#pragma unroll
    for (int nt = 0; nt < 4; nt++)
#pragma unroll
        for (int r = 0; r < 4; r++) o[nt][r] = 0.f;

    const float4* bt = (const float4*)bias_table +
        ((size_t)(((hl * 64 + tile) * 4 + w) * 32 + lane)) * NTILES;

    uint32_t* Pw = smu + OP + w * CP * 24;

    for (int c = 0; c < NC; c++) {
        __syncthreads();
        // ---- load K/V chunk: [pos][dim], packed STS.128 ----
        {
            const int e = tid & 7;
#pragma unroll 1
            for (int p = tid >> 3; p < CP; p += 16) {
                const int n = c * CP + p;
                const int uy = n / UXP, ux = n % UXP;
                const int y = uy0 + uy;
                const int x = min(ux0 + ux, WW - 1);
                const float* kp = &g_qkv[(size_t)((b * HH + y) * WW + x) * 768 + 256 + h * 32 + e * 4];
                float4 kv = __ldg((const float4*)kp);
                float4 vv = __ldg((const float4*)(kp + 256));
                uint4 kt = make_uint4(f2tf32(kv.x), f2tf32(kv.y), f2tf32(kv.z), f2tf32(kv.w));
                uint4 vt = make_uint4(f2tf32(vv.x), f2tf32(vv.y), f2tf32(vv.z), f2tf32(vv.w));
                *(uint4*)&smu[OK + p * 36 + 4 * e] = kt;
                *(uint4*)&smu[OV + p * 40 + 4 * e] = vt;
            }
        }
        __syncthreads();

        // ---- S = Q K^T ----
        float s[NT][4];
#pragma unroll
        for (int t = 0; t < NT; t++)
#pragma unroll
            for (int r = 0; r < 4; r++) s[t][r] = 0.f;
#pragma unroll
        for (int t = 0; t < NT; t++) {
#pragma unroll
            for (int kk = 0; kk < 4; kk++) {
                uint32_t b0 = smu[OK + (8 * t + lr) * 36 + 8 * kk + lc];
                uint32_t b1 = smu[OK + (8 * t + lr) * 36 + 8 * kk + lc + 4];
                asm volatile(
                    "mma.sync.aligned.m16n8k8.row.col.f32.tf32.tf32.f32 "
                    "{%0,%1,%2,%3}, {%4,%5,%6,%7}, {%8,%9}, {%0,%1,%2,%3};\n"
                    : "+f"(s[t][0]), "+f"(s[t][1]), "+f"(s[t][2]), "+f"(s[t][3])
                    : "r"(qf[kk][0]), "r"(qf[kk][1]), "r"(qf[kk][2]), "r"(qf[kk][3]),
                      "r"(b0), "r"(b1));
            }
        }
        // ---- + bias/mask (precomputed, frag-ordered) ----
#pragma unroll
        for (int t = 0; t < NT; t++) {
            float4 bv = __ldg(&bt[c * NT + t]);
            s[t][0] += bv.x; s[t][1] += bv.y; s[t][2] += bv.z; s[t][3] += bv.w;
        }
        // ---- online softmax ----
        float rm0 = -1e30f, rm1 = -1e30f;
#pragma unroll
        for (int t = 0; t < NT; t++) {
            rm0 = fmaxf(rm0, fmaxf(s[t][0], s[t][1]));
            rm1 = fmaxf(rm1, fmaxf(s[t][2], s[t][3]));
        }
        rm0 = fmaxf(rm0, __shfl_xor_sync(0xffffffffu, rm0, 1));
        rm0 = fmaxf(rm0, __shfl_xor_sync(0xffffffffu, rm0, 2));
        rm1 = fmaxf(rm1, __shfl_xor_sync(0xffffffffu, rm1, 1));
        rm1 = fmaxf(rm1, __shfl_xor_sync(0xffffffffu, rm1, 2));
        const float nm0 = fmaxf(mr0, rm0);
        const float nm1 = fmaxf(mr1, rm1);
        const float c0 = __expf(mr0 - nm0);
        const float c1 = __expf(mr1 - nm1);
        mr0 = nm0; mr1 = nm1;
        l0 *= c0; l1 *= c1;
#pragma unroll
        for (int nt = 0; nt < 4; nt++) {
            o[nt][0] *= c0; o[nt][1] *= c0;
            o[nt][2] *= c1; o[nt][3] *= c1;
        }
#pragma unroll
        for (int t = 0; t < NT; t++) {
            float p0 = __expf(s[t][0] - nm0);
            float p1 = __expf(s[t][1] - nm0);
            float p2 = __expf(s[t][2] - nm1);
            float p3 = __expf(s[t][3] - nm1);
            l0 += p0 + p1; l1 += p2 + p3;
            Pw[(8 * t + 2 * lc) * 24 + lr]         = f2tf32(p0);
            Pw[(8 * t + 2 * lc + 1) * 24 + lr]     = f2tf32(p1);
            Pw[(8 * t + 2 * lc) * 24 + lr + 8]     = f2tf32(p2);
            Pw[(8 * t + 2 * lc + 1) * 24 + lr + 8] = f2tf32(p3);
        }
        __syncwarp();
        // ---- O += P V ----
#pragma unroll
        for (int kk = 0; kk < NT; kk++) {
            uint32_t pa0 = Pw[(8 * kk + lc) * 24 + lr];
            uint32_t pa1 = Pw[(8 * kk + lc) * 24 + lr + 8];
            uint32_t pa2 = Pw[(8 * kk + lc + 4) * 24 + lr];
            uint32_t pa3 = Pw[(8 * kk + lc + 4) * 24 + lr + 8];
#pragma unroll
            for (int nt = 0; nt < 4; nt++) {
                uint32_t b0 = smu[OV + (8 * kk + lc) * 40 + 8 * nt + lr];
                uint32_t b1 = smu[OV + (8 * kk + lc + 4) * 40 + 8 * nt + lr];
                asm volatile(
                    "mma.sync.aligned.m16n8k8.row.col.f32.tf32.tf32.f32 "
                    "{%0,%1,%2,%3}, {%4,%5,%6,%7}, {%8,%9}, {%0,%1,%2,%3};\n"
                    : "+f"(o[nt][0]), "+f"(o[nt][1]), "+f"(o[nt][2]), "+f"(o[nt][3])
                    : "r"(pa0), "r"(pa1), "r"(pa2), "r"(pa3), "r"(b0), "r"(b1));
            }
        }
        __syncwarp();
    }

    // ---- finalize ----
    l0 += __shfl_xor_sync(0xffffffffu, l0, 1);
    l0 += __shfl_xor_sync(0xffffffffu, l0, 2);
    l1 += __shfl_xor_sync(0xffffffffu, l1, 1);
    l1 += __shfl_xor_sync(0xffffffffu, l1, 2);
    const float inv0 = 1.f / l0;
    const float inv1 = 1.f / l1;
    const int i0 = ty * 8 + 2 * w;
    const int j  = tx * 8 + lr;
    float* y0 = &g_y[(size_t)((b * HH + i0) * WW + j) * 256 + h * 32];
    float* y1 = &g_y[(size_t)((b * HH + i0 + 1) * WW + j) * 256 + h * 32];
#pragma unroll
    for (int nt = 0; nt < 4; nt++) {
        const int d = 8 * nt + 2 * lc;
        *(float2*)&y0[d] = make_float2(o[nt][0] * inv0, o[nt][1] * inv0);
        *(float2*)&y1[d] = make_float2(o[nt][2] * inv1, o[nt][3] * inv1);
    }
}

// ---------------------------------------------------------------------------
extern "C" void kernel_launch(void* const* d_in, const int* in_sizes, int n_in,
                              void* d_out, int out_size)
{
    const float* x      = (const float*)d_in[0];
    const float* w_qkv  = (const float*)d_in[1];
    const float* b_qkv  = (const float*)d_in[2];
    const float* rpb0   = (const float*)d_in[3];
    const float* rpb1   = (const float*)d_in[4];
    const float* w_proj = (const float*)d_in[5];
    const float* b_proj = (const float*)d_in[6];
    float* out = (float*)d_out;

    float *qkv = nullptr, *y = nullptr, *bt7 = nullptr, *bt13 = nullptr;
    cudaGetSymbolAddress((void**)&qkv,  g_qkv);
    cudaGetSymbolAddress((void**)&y,    g_y);
    cudaGetSymbolAddress((void**)&bt7,  g_bias7);
    cudaGetSymbolAddress((void**)&bt13, g_bias13);

    // smem sizes: K=7: (2304 + 56*36 + 56*40 + 4*56*24) * 4 = 47744 B
    //             K=13: (2304 + 80*36 + 80*40 + 4*80*24) * 4 = 64256 B
    cudaFuncSetAttribute(natten_mma<7, 16, 14, 7, 4>,
                         cudaFuncAttributeMaxDynamicSharedMemorySize, 49152);
    cudaFuncSetAttribute(natten_mma<13, 24, 20, 10, 6>,
                         cudaFuncAttributeMaxDynamicSharedMemorySize, 66560);

    // bias/mask tables (batch-independent, frag-ordered)
    bias_precompute<7, 16, 14, 28><<<3584, 256>>>(rpb0, bt7);
    bias_precompute<13, 24, 20, 60><<<7680, 256>>>(rpb1, bt13);

    // 1) QKV GEMM
    gemm_tf32<<<dim3(6, 256), 256>>>(x, w_qkv, b_qkv, qkv, 256, 768);

    // 2) tensor-core neighborhood attention (split heads)
    natten_mma<7, 16, 14, 7, 4>
        <<<dim3(64, 4, 8), 128, 47744>>>(bt7, 0);
    natten_mma<13, 24, 20, 10, 6>
        <<<dim3(64, 4, 8), 128, 64256>>>(bt13, 4);

    // 3) Projection GEMM
    gemm_tf32<<<dim3(2, 256), 256>>>(y, w_proj, b_proj, out, 256, 256);
}

// round 7
// speedup vs baseline: 5.1650x; 1.1136x over previous
#include <cuda_runtime.h>
#include <cstdint>

#define BB 8
#define HH 64
#define WW 64

// Scratch: qkv [32768 x 768] (tf32-rounded bits, q pre-scaled), y [32768 x 256],
// bias tables in mma-frag order.
__device__ float g_qkv[25165824];
__device__ float g_y[8388608];
__device__ float g_bias7[3670016];   // 4h*64t*4w*32l*28nt*4
__device__ float g_bias13[7864320];  // 4h*64t*4w*32l*60nt*4

__device__ __forceinline__ uint32_t f2tf32(float x) {
    uint32_t u;
    asm("cvt.rna.tf32.f32 %0, %1;" : "=r"(u) : "f"(x));
    return u;
}
__device__ __forceinline__ int iclamp(int v, int lo, int hi) {
    return min(max(v, lo), hi);
}
__device__ __forceinline__ uint32_t smem_u32(const void* p) {
    uint32_t a;
    asm("{ .reg .u64 t; cvta.to.shared.u64 t, %1; cvt.u32.u64 %0, t; }"
        : "=r"(a) : "l"(p));
    return a;
}

// ---------------------------------------------------------------------------
// GEMM: C[M,N] = A[M,K]*B[N,K]^T + bias, tf32 mma, double-buffered smem.
// qmode=1: cols<256 scaled by qscale, all cols rna-rounded to tf32 bits.
// ---------------------------------------------------------------------------
__global__ __launch_bounds__(256)
void gemm_tf32(const float* __restrict__ A, const float* __restrict__ B,
               const float* __restrict__ bias, float* __restrict__ C,
               int Kd, int Nd, int qmode, float qscale)
{
    __shared__ uint32_t As[2][16][132];
    __shared__ uint32_t Bs[2][16][132];
    const int bm = blockIdx.y << 7;
    const int bn = blockIdx.x << 7;
    const int tid = threadIdx.x;

    const int lrow = tid >> 2;
    const int lkc  = (tid & 3) << 2;
    const float* Ap0 = A + (size_t)(bm + lrow) * Kd + lkc;
    const float* Ap1 = A + (size_t)(bm + lrow + 64) * Kd + lkc;
    const float* Bp0 = B + (size_t)(bn + lrow) * Kd + lkc;
    const float* Bp1 = B + (size_t)(bn + lrow + 64) * Kd + lkc;

    const int wid = tid >> 5;
    const int lane = tid & 31;
    const int wm = (wid >> 1) << 5;
    const int wn = (wid & 1) << 6;
    const int lr = lane >> 2;
    const int lc = lane & 3;

    float acc[2][8][4];
#pragma unroll
    for (int mt = 0; mt < 2; mt++)
#pragma unroll
        for (int nt = 0; nt < 8; nt++)
#pragma unroll
            for (int r = 0; r < 4; r++) acc[mt][nt][r] = 0.f;

    float4 ra0 = *(const float4*)(Ap0);
    float4 ra1 = *(const float4*)(Ap1);
    float4 rb0 = *(const float4*)(Bp0);
    float4 rb1 = *(const float4*)(Bp1);

#define GSTORE(st)                                                        \
    do {                                                                  \
        As[st][lkc + 0][lrow] = f2tf32(ra0.x);                            \
        As[st][lkc + 1][lrow] = f2tf32(ra0.y);                            \
        As[st][lkc + 2][lrow] = f2tf32(ra0.z);                            \
        As[st][lkc + 3][lrow] = f2tf32(ra0.w);                            \
        As[st][lkc + 0][lrow + 64] = f2tf32(ra1.x);                       \
        As[st][lkc + 1][lrow + 64] = f2tf32(ra1.y);                       \
        As[st][lkc + 2][lrow + 64] = f2tf32(ra1.z);                       \
        As[st][lkc + 3][lrow + 64] = f2tf32(ra1.w);                       \
        Bs[st][lkc + 0][lrow] = f2tf32(rb0.x);                            \
        Bs[st][lkc + 1][lrow] = f2tf32(rb0.y);                            \
        Bs[st][lkc + 2][lrow] = f2tf32(rb0.z);                            \
        Bs[st][lkc + 3][lrow] = f2tf32(rb0.w);                            \
        Bs[st][lkc + 0][lrow + 64] = f2tf32(rb1.x);                       \
        Bs[st][lkc + 1][lrow + 64] = f2tf32(rb1.y);                       \
        Bs[st][lkc + 2][lrow + 64] = f2tf32(rb1.z);                       \
        Bs[st][lkc + 3][lrow + 64] = f2tf32(rb1.w);                       \
    } while (0)

    GSTORE(0);
    __syncthreads();

    const int NIT = Kd >> 4;
    for (int it = 0; it < NIT; it++) {
        const int cur = it & 1;
        if (it + 1 < NIT) {
            const int ko = (it + 1) << 4;
            ra0 = *(const float4*)(Ap0 + ko);
            ra1 = *(const float4*)(Ap1 + ko);
            rb0 = *(const float4*)(Bp0 + ko);
            rb1 = *(const float4*)(Bp1 + ko);
        }
#pragma unroll
        for (int kk = 0; kk < 16; kk += 8) {
            uint32_t af[2][4];
#pragma unroll
            for (int mt = 0; mt < 2; mt++) {
                const int m0 = wm + (mt << 4);
                af[mt][0] = As[cur][kk + lc][m0 + lr];
                af[mt][1] = As[cur][kk + lc][m0 + lr + 8];
                af[mt][2] = As[cur][kk + lc + 4][m0 + lr];
                af[mt][3] = As[cur][kk + lc + 4][m0 + lr + 8];
            }
#pragma unroll
            for (int nt = 0; nt < 8; nt++) {
                const int n0 = wn + (nt << 3);
                uint32_t b0 = Bs[cur][kk + lc][n0 + lr];
                uint32_t b1 = Bs[cur][kk + lc + 4][n0 + lr];
#pragma unroll
                for (int mt = 0; mt < 2; mt++) {
                    asm volatile(
                        "mma.sync.aligned.m16n8k8.row.col.f32.tf32.tf32.f32 "
                        "{%0,%1,%2,%3}, {%4,%5,%6,%7}, {%8,%9}, {%0,%1,%2,%3};\n"
                        : "+f"(acc[mt][nt][0]), "+f"(acc[mt][nt][1]),
                          "+f"(acc[mt][nt][2]), "+f"(acc[mt][nt][3])
                        : "r"(af[mt][0]), "r"(af[mt][1]), "r"(af[mt][2]), "r"(af[mt][3]),
                          "r"(b0), "r"(b1));
                }
            }
        }
        if (it + 1 < NIT) GSTORE(cur ^ 1);
        __syncthreads();
    }
#undef GSTORE

#pragma unroll
    for (int nt = 0; nt < 8; nt++) {
        const int col = bn + wn + (nt << 3) + (lc << 1);
        const float bx = __ldg(&bias[col]);
        const float by = __ldg(&bias[col + 1]);
#pragma unroll
        for (int mt = 0; mt < 2; mt++) {
            const int row = bm + wm + (mt << 4) + lr;
            float v0 = acc[mt][nt][0] + bx;
            float v1 = acc[mt][nt][1] + by;
            float v2 = acc[mt][nt][2] + bx;
            float v3 = acc[mt][nt][3] + by;
            if (qmode) {
                const float sc = (col < 256) ? qscale : 1.f;
                v0 = __uint_as_float(f2tf32(v0 * sc));
                v1 = __uint_as_float(f2tf32(v1 * sc));
                v2 = __uint_as_float(f2tf32(v2 * sc));
                v3 = __uint_as_float(f2tf32(v3 * sc));
            }
            *(float2*)&C[(size_t)row * Nd + col] = make_float2(v0, v1);
            *(float2*)&C[(size_t)(row + 8) * Nd + col] = make_float2(v2, v3);
        }
    }
}

// ---------------------------------------------------------------------------
// Bias+mask table precompute (unchanged).
// ---------------------------------------------------------------------------
template<int K, int UXP, int UXR, int NTILES>
__global__ __launch_bounds__(256)
void bias_precompute(const float* __restrict__ rpb, float* __restrict__ table)
{
    constexpr int NH = K / 2;
    constexpr int RP = 2 * K - 1;
    constexpr int UY = K + 7;
    const int gid = blockIdx.x * 256 + threadIdx.x;
    const int total = 4 * 64 * 128 * NTILES;
    if (gid >= total) return;
    const int t    = gid % NTILES;
    int r1 = gid / NTILES;
    const int lane = r1 & 31; r1 >>= 5;
    const int w    = r1 & 3;  r1 >>= 2;
    const int tile = r1 & 63; r1 >>= 6;
    const int h    = r1;
    const int ty = tile >> 3, tx = tile & 7;
    const int lr = lane >> 2, lc = lane & 3;
    const int uy0 = iclamp(ty * 8 - NH, 0, HH - UY);
    const int ux0 = iclamp(tx * 8 - NH, 0, WW - UY);

    float v[4];
#pragma unroll
    for (int r = 0; r < 4; r++) {
        const int m = w * 16 + lr + ((r >> 1) << 3);
        const int n = t * 8 + (lc << 1) + (r & 1);
        const int i = ty * 8 + (m >> 3);
        const int j = tx * 8 + (m & 7);
        const int si = iclamp(i - NH, 0, HH - K);
        const int sj = iclamp(j - NH, 0, WW - K);
        const int uy = n / UXP, ux = n % UXP;
        const int y = uy0 + uy, x = ux0 + ux;
        bool ok = (ux < UXR) && (y >= si) && (y < si + K) && (x >= sj) && (x < sj + K);
        v[r] = ok ? rpb[((size_t)h * RP + (y - i + K - 1)) * RP + (x - j + K - 1)]
                  : -1e30f;
    }
    *(float4*)&table[(size_t)gid * 4] = make_float4(v[0], v[1], v[2], v[3]);
}

// ---------------------------------------------------------------------------
// Tensor-core NATTEN. qkv is pre-rounded tf32 bits (q pre-scaled), so
// staging is pure cp.async 16B. P stays in registers: S-accum -> A-frag via
// 8 in-quad SHFL + 4 selects per n-tile. smem: Qs[32][72], Ks[CP][36],
// Vs[CP][40] only.
// ---------------------------------------------------------------------------
template<int K, int UXP, int UXR, int NT, int NC>
__global__ __launch_bounds__(128)
void natten_mma(const float* __restrict__ bias_table, int head0)
{
    constexpr int NH = K / 2;
    constexpr int UY = K + 7;
    constexpr int CP = NT * 8;        // keys per chunk
    constexpr int NTILES = NT * NC;
    constexpr int OQ = 0;             // Qs[32][72]
    constexpr int OK = 2304;          // Ks[CP][36]
    constexpr int OV = OK + CP * 36;  // Vs[CP][40]

    extern __shared__ float sm[];
    uint32_t* smu = (uint32_t*)sm;
    const uint32_t sb = smem_u32(sm);

    const int b    = blockIdx.z;
    const int hl   = blockIdx.y;
    const int h    = head0 + hl;
    const int tile = blockIdx.x;
    const int ty = tile >> 3, tx = tile & 7;
    const int uy0 = iclamp(ty * 8 - NH, 0, HH - UY);
    const int ux0 = iclamp(tx * 8 - NH, 0, WW - UY);

    const int tid  = threadIdx.x;
    const int w    = tid >> 5;
    const int lane = tid & 31;
    const int lr = lane >> 2, lc = lane & 3;
    const int m0 = w << 4;

    // ---- stage Q (already scaled + tf32 bits) into Qs[k][m], stride 72 ----
    {
        const int qm = tid >> 1;
        const int kh = (tid & 1) << 4;
        const int qi = ty * 8 + (qm >> 3);
        const int qj = tx * 8 + (qm & 7);
        const uint4* qp = (const uint4*)&g_qkv[(size_t)((b * HH + qi) * WW + qj) * 768 + h * 32 + kh];
#pragma unroll
        for (int v4 = 0; v4 < 4; v4++) {
            uint4 qv = __ldg(&qp[v4]);
            smu[OQ + (kh + v4 * 4 + 0) * 72 + qm] = qv.x;
            smu[OQ + (kh + v4 * 4 + 1) * 72 + qm] = qv.y;
            smu[OQ + (kh + v4 * 4 + 2) * 72 + qm] = qv.z;
            smu[OQ + (kh + v4 * 4 + 3) * 72 + qm] = qv.w;
        }
    }
    __syncthreads();

    uint32_t qf[4][4];
#pragma unroll
    for (int s = 0; s < 4; s++) {
        qf[s][0] = smu[OQ + (8 * s + lc) * 72 + m0 + lr];
        qf[s][1] = smu[OQ + (8 * s + lc) * 72 + m0 + lr + 8];
        qf[s][2] = smu[OQ + (8 * s + lc + 4) * 72 + m0 + lr];
        qf[s][3] = smu[OQ + (8 * s + lc + 4) * 72 + m0 + lr + 8];
    }

    float mr0 = -1e28f, mr1 = -1e28f, l0 = 0.f, l1 = 0.f;
    float o[4][4];
#pragma unroll
    for (int nt = 0; nt < 4; nt++)
#pragma unroll
        for (int r = 0; r < 4; r++) o[nt][r] = 0.f;

    const float4* bt = (const float4*)bias_table +
        ((size_t)(((hl * 64 + tile) * 4 + w) * 32 + lane)) * NTILES;

    // shfl transpose constants (S accum frag -> P A-frag)
    const int s1 = (lane & 28) | ((lane & 3) >> 1);
    const int s2 = s1 + 2;
    const bool oddc = (lane & 1);

    for (int c = 0; c < NC; c++) {
        __syncthreads();
        // ---- stage K/V chunk via cp.async (pure copy, pre-rounded) ----
        {
            const int e = tid & 7;
#pragma unroll 1
            for (int p = tid >> 3; p < CP; p += 16) {
                const int n = c * CP + p;
                const int uy = n / UXP, ux = n % UXP;
                const int y = uy0 + uy;
                const int x = min(ux0 + ux, WW - 1);
                const float* kp = &g_qkv[(size_t)((b * HH + y) * WW + x) * 768 + 256 + h * 32 + e * 4];
                const uint32_t ks = sb + (uint32_t)(OK + p * 36 + 4 * e) * 4u;
                const uint32_t vs = sb + (uint32_t)(OV + p * 40 + 4 * e) * 4u;
                asm volatile("cp.async.ca.shared.global [%0], [%1], 16;" :: "r"(ks), "l"(kp));
                asm volatile("cp.async.ca.shared.global [%0], [%1], 16;" :: "r"(vs), "l"(kp + 256));
            }
            asm volatile("cp.async.commit_group;");
            asm volatile("cp.async.wait_group 0;");
        }
        __syncthreads();

        // ---- S = Q K^T ----
        float s[NT][4];
#pragma unroll
        for (int t = 0; t < NT; t++)
#pragma unroll
            for (int r = 0; r < 4; r++) s[t][r] = 0.f;
#pragma unroll
        for (int t = 0; t < NT; t++) {
#pragma unroll
            for (int kk = 0; kk < 4; kk++) {
                uint32_t b0 = smu[OK + (8 * t + lr) * 36 + 8 * kk + lc];
                uint32_t b1 = smu[OK + (8 * t + lr) * 36 + 8 * kk + lc + 4];
                asm volatile(
                    "mma.sync.aligned.m16n8k8.row.col.f32.tf32.tf32.f32 "
                    "{%0,%1,%2,%3}, {%4,%5,%6,%7}, {%8,%9}, {%0,%1,%2,%3};\n"
                    : "+f"(s[t][0]), "+f"(s[t][1]), "+f"(s[t][2]), "+f"(s[t][3])
                    : "r"(qf[kk][0]), "r"(qf[kk][1]), "r"(qf[kk][2]), "r"(qf[kk][3]),
                      "r"(b0), "r"(b1));
            }
        }
        // ---- + bias/mask ----
#pragma unroll
        for (int t = 0; t < NT; t++) {
            float4 bv = __ldg(&bt[c * NT + t]);
            s[t][0] += bv.x; s[t][1] += bv.y; s[t][2] += bv.z; s[t][3] += bv.w;
        }
        // ---- online softmax ----
        float rm0 = -1e30f, rm1 = -1e30f;
#pragma unroll
        for (int t = 0; t < NT; t++) {
            rm0 = fmaxf(rm0, fmaxf(s[t][0], s[t][1]));
            rm1 = fmaxf(rm1, fmaxf(s[t][2], s[t][3]));
        }
        rm0 = fmaxf(rm0, __shfl_xor_sync(0xffffffffu, rm0, 1));
        rm0 = fmaxf(rm0, __shfl_xor_sync(0xffffffffu, rm0, 2));
        rm1 = fmaxf(rm1, __shfl_xor_sync(0xffffffffu, rm1, 1));
        rm1 = fmaxf(rm1, __shfl_xor_sync(0xffffffffu, rm1, 2));
        const float nm0 = fmaxf(mr0, rm0);
        const float nm1 = fmaxf(mr1, rm1);
        const float c0 = __expf(mr0 - nm0);
        const float c1 = __expf(mr1 - nm1);
        mr0 = nm0; mr1 = nm1;
        l0 *= c0; l1 *= c1;
#pragma unroll
        for (int nt = 0; nt < 4; nt++) {
            o[nt][0] *= c0; o[nt][1] *= c0;
            o[nt][2] *= c1; o[nt][3] *= c1;
        }
        // ---- exp -> P A-frag via shfl -> PV mma, per n-tile ----
#pragma unroll
        for (int t = 0; t < NT; t++) {
            const float p0 = __expf(s[t][0] - nm0);
            const float p1 = __expf(s[t][1] - nm0);
            const float p2 = __expf(s[t][2] - nm1);
            const float p3 = __expf(s[t][3] - nm1);
            l0 += p0 + p1; l1 += p2 + p3;
            const uint32_t u0 = f2tf32(p0), u1 = f2tf32(p1);
            const uint32_t u2 = f2tf32(p2), u3 = f2tf32(p3);
            const uint32_t x0 = __shfl_sync(0xffffffffu, u0, s1);
            const uint32_t y0 = __shfl_sync(0xffffffffu, u1, s1);
            const uint32_t x1 = __shfl_sync(0xffffffffu, u2, s1);
            const uint32_t y1 = __shfl_sync(0xffffffffu, u3, s1);
            const uint32_t x2 = __shfl_sync(0xffffffffu, u0, s2);
            const uint32_t y2 = __shfl_sync(0xffffffffu, u1, s2);
            const uint32_t x3 = __shfl_sync(0xffffffffu, u2, s2);
            const uint32_t y3 = __shfl_sync(0xffffffffu, u3, s2);
            const uint32_t pa0 = oddc ? y0 : x0;
            const uint32_t pa1 = oddc ? y1 : x1;
            const uint32_t pa2 = oddc ? y2 : x2;
            const uint32_t pa3 = oddc ? y3 : x3;
#pragma unroll
            for (int nt = 0; nt < 4; nt++) {
                uint32_t b0 = smu[OV + (8 * t + lc) * 40 + 8 * nt + lr];
                uint32_t b1 = smu[OV + (8 * t + lc + 4) * 40 + 8 * nt + lr];
                asm volatile(
                    "mma.sync.aligned.m16n8k8.row.col.f32.tf32.tf32.f32 "
                    "{%0,%1,%2,%3}, {%4,%5,%6,%7}, {%8,%9}, {%0,%1,%2,%3};\n"
                    : "+f"(o[nt][0]), "+f"(o[nt][1]), "+f"(o[nt][2]), "+f"(o[nt][3])
                    : "r"(pa0), "r"(pa1), "r"(pa2), "r"(pa3), "r"(b0), "r"(b1));
            }
        }
    }

    // ---- finalize ----
    l0 += __shfl_xor_sync(0xffffffffu, l0, 1);
    l0 += __shfl_xor_sync(0xffffffffu, l0, 2);
    l1 += __shfl_xor_sync(0xffffffffu, l1, 1);
    l1 += __shfl_xor_sync(0xffffffffu, l1, 2);
    const float inv0 = 1.f / l0;
    const float inv1 = 1.f / l1;
    const int i0 = ty * 8 + 2 * w;
    const int j  = tx * 8 + lr;
    float* y0 = &g_y[(size_t)((b * HH + i0) * WW + j) * 256 + h * 32];
    float* y1 = &g_y[(size_t)((b * HH + i0 + 1) * WW + j) * 256 + h * 32];
#pragma unroll
    for (int nt = 0; nt < 4; nt++) {
        const int d = 8 * nt + 2 * lc;
        *(float2*)&y0[d] = make_float2(o[nt][0] * inv0, o[nt][1] * inv0);
        *(float2*)&y1[d] = make_float2(o[nt][2] * inv1, o[nt][3] * inv1);
    }
}

// ---------------------------------------------------------------------------
extern "C" void kernel_launch(void* const* d_in, const int* in_sizes, int n_in,
                              void* d_out, int out_size)
{
    const float* x      = (const float*)d_in[0];
    const float* w_qkv  = (const float*)d_in[1];
    const float* b_qkv  = (const float*)d_in[2];
    const float* rpb0   = (const float*)d_in[3];
    const float* rpb1   = (const float*)d_in[4];
    const float* w_proj = (const float*)d_in[5];
    const float* b_proj = (const float*)d_in[6];
    float* out = (float*)d_out;

    float *qkv = nullptr, *y = nullptr, *bt7 = nullptr, *bt13 = nullptr;
    cudaGetSymbolAddress((void**)&qkv,  g_qkv);
    cudaGetSymbolAddress((void**)&y,    g_y);
    cudaGetSymbolAddress((void**)&bt7,  g_bias7);
    cudaGetSymbolAddress((void**)&bt13, g_bias13);

    // bias/mask tables (batch-independent, frag-ordered)
    bias_precompute<7, 16, 14, 28><<<3584, 256>>>(rpb0, bt7);
    bias_precompute<13, 24, 20, 60><<<7680, 256>>>(rpb1, bt13);

    // 1) QKV GEMM (epilogue pre-scales q and rounds q/k/v to tf32 bits)
    gemm_tf32<<<dim3(6, 256), 256>>>(x, w_qkv, b_qkv, qkv, 256, 768,
                                     1, 0.17677669529663687f);

    // 2) tensor-core neighborhood attention (split heads)
    // smem: K7: (2304 + 56*36 + 56*40)*4 = 26240 B
    //       K13: (2304 + 80*36 + 80*40)*4 = 33536 B
    natten_mma<7, 16, 14, 7, 4>
        <<<dim3(64, 4, 8), 128, 26240>>>(bt7, 0);
    natten_mma<13, 24, 20, 10, 6>
        <<<dim3(64, 4, 8), 128, 33536>>>(bt13, 4);

    // 3) Projection GEMM (plain fp32 epilogue)
    gemm_tf32<<<dim3(2, 256), 256>>>(y, w_proj, b_proj, out, 256, 256, 0, 0.f);
}